// round 7
// baseline (speedup 1.0000x reference)
#include <cuda_runtime.h>

#define A_COEF 0.01f
#define B_COEF 4.81f
#define C_COEF 0.0f
#define OOB_COST 3.0f

#define ROWS_PER_THREAD 8
#define BLOCK 256

__device__ __forceinline__ float penal(float v) {
    float cost = C_COEF + A_COEF * __expf(B_COEF * (1.0f + v));
    bool in_bounds = (v >= 0.0f) && (v <= 1.0f);
    return in_bounds ? cost : OOB_COST;
}

__global__ void __launch_bounds__(BLOCK) penalizer_kernel(
    const float* __restrict__ X, float* __restrict__ out, int n_rows)
{
    // Block-interleaved: each iteration j, a warp's 32 lanes read 32 CONSECUTIVE
    // rows (1024B contiguous) -> 8 x 128B lines per warp-LDG (minimal L1tex
    // wavefronts). 8 front-batched streaming loads per thread for MLP;
    // write-through stores keep the 64MB write stream out of L2's dirty set.
    long long blockBase = (long long)blockIdx.x * (BLOCK * ROWS_PER_THREAD);

    if (blockBase + BLOCK * ROWS_PER_THREAD <= n_rows) {
        float v[ROWS_PER_THREAD];
        #pragma unroll
        for (int j = 0; j < ROWS_PER_THREAD; ++j) {
            long long row = blockBase + j * BLOCK + threadIdx.x;
            v[j] = __ldcs(X + row * 8 + 7);
        }
        #pragma unroll
        for (int j = 0; j < ROWS_PER_THREAD; ++j) {
            long long row = blockBase + j * BLOCK + threadIdx.x;
            __stwt(out + row, penal(v[j]));
        }
    } else {
        // tail block (not hit when n_rows % (BLOCK*ROWS_PER_THREAD) == 0)
        for (int j = 0; j < ROWS_PER_THREAD; ++j) {
            long long row = blockBase + j * BLOCK + threadIdx.x;
            if (row < n_rows) {
                out[row] = penal(__ldcs(X + row * 8 + 7));
            }
        }
    }
}

extern "C" void kernel_launch(void* const* d_in, const int* in_sizes, int n_in,
                              void* d_out, int out_size)
{
    const float* X = (const float*)d_in[0];
    float* out = (float*)d_out;
    int n_rows = in_sizes[0] / 8;          // [N, 8] fp32
    long long rows_per_block = (long long)BLOCK * ROWS_PER_THREAD;
    int grid = (int)((n_rows + rows_per_block - 1) / rows_per_block);
    penalizer_kernel<<<grid, BLOCK>>>(X, out, n_rows);
}

// round 8
// speedup vs baseline: 1.0061x; 1.0061x over previous
#include <cuda_runtime.h>

#define A_COEF 0.01f
#define B_COEF 4.81f
#define C_COEF 0.0f
#define OOB_COST 3.0f

#define ROWS_PER_THREAD 8
#define BLOCK 512

__device__ __forceinline__ float penal(float v) {
    float cost = C_COEF + A_COEF * __expf(B_COEF * (1.0f + v));
    bool in_bounds = (v >= 0.0f) && (v <= 1.0f);
    return in_bounds ? cost : OOB_COST;
}

__global__ void __launch_bounds__(BLOCK) penalizer_kernel(
    const float* __restrict__ X, float* __restrict__ out, int n_rows)
{
    // Block-interleaved: each iteration j, a warp's 32 lanes read 32 CONSECUTIVE
    // rows (1024B contiguous) -> 8 x 128B lines per warp-LDG (minimal L1tex
    // wavefronts). 8 front-batched streaming loads per thread for MLP;
    // write-through stores keep the 64MB write stream out of L2's dirty set.
    long long blockBase = (long long)blockIdx.x * (BLOCK * ROWS_PER_THREAD);

    if (blockBase + BLOCK * ROWS_PER_THREAD <= n_rows) {
        float v[ROWS_PER_THREAD];
        #pragma unroll
        for (int j = 0; j < ROWS_PER_THREAD; ++j) {
            long long row = blockBase + j * BLOCK + threadIdx.x;
            v[j] = __ldcs(X + row * 8 + 7);
        }
        #pragma unroll
        for (int j = 0; j < ROWS_PER_THREAD; ++j) {
            long long row = blockBase + j * BLOCK + threadIdx.x;
            __stwt(out + row, penal(v[j]));
        }
    } else {
        // tail block (not hit when n_rows % (BLOCK*ROWS_PER_THREAD) == 0)
        for (int j = 0; j < ROWS_PER_THREAD; ++j) {
            long long row = blockBase + j * BLOCK + threadIdx.x;
            if (row < n_rows) {
                out[row] = penal(__ldcs(X + row * 8 + 7));
            }
        }
    }
}

extern "C" void kernel_launch(void* const* d_in, const int* in_sizes, int n_in,
                              void* d_out, int out_size)
{
    const float* X = (const float*)d_in[0];
    float* out = (float*)d_out;
    int n_rows = in_sizes[0] / 8;          // [N, 8] fp32
    long long rows_per_block = (long long)BLOCK * ROWS_PER_THREAD;
    int grid = (int)((n_rows + rows_per_block - 1) / rows_per_block);
    penalizer_kernel<<<grid, BLOCK>>>(X, out, n_rows);
}